// round 16
// baseline (speedup 1.0000x reference)
#include <cuda_runtime.h>

#define IMG_H 256
#define IMG_W 256
#define KS    33
#define PADV  16
#define TX    32
#define TY    8
#define TILE_W TX                    // 32 (one pixel per thread)
#define PW1   (TILE_W + KS - 1)      // 64 patch width
#define PLANE (IMG_H * IMG_W)        // 65536

#define PH_SUB TY                    // fh fixed per CTA -> 8 patch rows

__global__ void zero_out_kernel(float* __restrict__ out)
{
    int i = blockIdx.x * blockDim.x + threadIdx.x;
    ((float4*)out)[i] = make_float4(0.f, 0.f, 0.f, 0.f);
}

__global__ __launch_bounds__(TX * TY, 8)
void reblur_dynconv_v1_kernel(const float* __restrict__ img,
                              const float* __restrict__ ker,
                              float* __restrict__ out)
{
    __shared__ float s0[PH_SUB * PW1];
    __shared__ float s1[PH_SUB * PW1];
    __shared__ float s2[PH_SUB * PW1];

    const int lx  = threadIdx.x;
    const int ly  = threadIdx.y;
    const int tid = ly * TX + lx;
    const int bx0 = blockIdx.x * TILE_W;
    const int by0 = blockIdx.y * TY;
    const int fh  = blockIdx.z;              // single kernel row per CTA

    // Stage replication-padded rows [by0+fh-PAD, +8) x [bx0-PAD, +64), 3 ch.
    // 512 floats = exactly 2 strided iterations. Image is 768 KB -> L2 hits.
    #pragma unroll
    for (int k = 0; k < (PH_SUB * PW1) / (TX * TY); ++k) {
        const int i  = k * (TX * TY) + tid;
        const int py = i >> 6;               // / 64
        const int px = i & 63;
        int gy = by0 + fh + py - PADV;
        int gx = bx0 + px - PADV;
        gy = gy < 0 ? 0 : (gy > IMG_H - 1 ? IMG_H - 1 : gy);
        gx = gx < 0 ? 0 : (gx > IMG_W - 1 ? IMG_W - 1 : gx);
        const int gi = gy * IMG_W + gx;
        s0[i] = img[gi];
        s1[i] = img[PLANE + gi];
        s2[i] = img[2 * PLANE + gi];
    }
    __syncthreads();

    const int x   = bx0 + lx;
    const int y   = by0 + ly;
    const int pix = y * IMG_W + x;
    // Weights for taps (fh, fw): planes fh*33 + fw, fw = 0..32, stride PLANE.
    const float* __restrict__ kr = ker + (size_t)(fh * KS) * PLANE + pix;

    // fh fixed -> each thread reads only its own smem row (sliding window).
    const float* __restrict__ r0 = &s0[ly * PW1 + lx];
    const float* __restrict__ r1 = &s1[ly * PW1 + lx];
    const float* __restrict__ r2 = &s2[ly * PW1 + lx];

    float a0 = 0.f, a1 = 0.f, a2 = 0.f;

    #pragma unroll
    for (int fw = 0; fw < KS; ++fw) {
        float w = kr[(size_t)fw * PLANE];    // 128B/warp, coalesced stream
        w = (w > 1e-4f) ? w : 0.0f;
        a0 = fmaf(w, r0[fw], a0);
        a1 = fmaf(w, r1[fw], a1);
        a2 = fmaf(w, r2[fw], a2);
    }

    atomicAdd(&out[pix],             a0);
    atomicAdd(&out[PLANE + pix],     a1);
    atomicAdd(&out[2 * PLANE + pix], a2);
}

extern "C" void kernel_launch(void* const* d_in, const int* in_sizes, int n_in,
                              void* d_out, int out_size)
{
    const float* img = (const float*)d_in[0];   // [1,3,256,256]
    const float* ker = (const float*)d_in[1];   // [1,1089,256,256]
    float* out = (float*)d_out;                 // [1,3,256,256]

    zero_out_kernel<<<(3 * PLANE / 4) / 256, 256>>>(out);

    dim3 block(TX, TY);
    dim3 grid(IMG_W / TILE_W, IMG_H / TY, KS);  // 8 x 32 x 33 = 8448 CTAs
    reblur_dynconv_v1_kernel<<<grid, block>>>(img, ker, out);
}